// round 15
// baseline (speedup 1.0000x reference)
#include <cuda_runtime.h>
#include <math.h>

#define NTOK 4096   // B*S
#define EDIM 1024
#define FDIM 4096
#define SEQ  2048
#define NB   2
#define NH   16
#define HDIM 64

// Scratch (allocation-free rule: static __device__ globals)
__device__ float g_h  [NTOK * EDIM];      // LN1 / LN2 output (reused)
__device__ float g_qkv[NTOK * 3 * EDIM];  // fused qkv
__device__ float g_o  [NTOK * EDIM];      // attention output
__device__ float g_x1 [NTOK * EDIM];      // residual after attention
__device__ float g_ff [NTOK * FDIM];      // FF1 output

// ---------------------------------------------------------------------------
// LayerNorm over last dim (1024). One block per row, 256 threads, one float4
// per thread.
// ---------------------------------------------------------------------------
__global__ __launch_bounds__(256) void ln_kernel(
    const float* __restrict__ x, const float* __restrict__ g,
    const float* __restrict__ b, float* __restrict__ y)
{
    const int row = blockIdx.x;
    const int tid = threadIdx.x;
    const float* xr = x + (long long)row * EDIM;

    float4 v = *(const float4*)(xr + tid * 4);
    float s  = v.x + v.y + v.z + v.w;
    float ss = v.x * v.x + v.y * v.y + v.z * v.z + v.w * v.w;

    #pragma unroll
    for (int o = 16; o; o >>= 1) {
        s  += __shfl_xor_sync(0xffffffffu, s,  o);
        ss += __shfl_xor_sync(0xffffffffu, ss, o);
    }
    __shared__ float sh_s[8], sh_ss[8];
    const int w = tid >> 5, l = tid & 31;
    if (l == 0) { sh_s[w] = s; sh_ss[w] = ss; }
    __syncthreads();

    float tot = 0.f, tot2 = 0.f;
    #pragma unroll
    for (int i = 0; i < 8; i++) { tot += sh_s[i]; tot2 += sh_ss[i]; }

    const float mu  = tot  * (1.f / EDIM);
    const float var = tot2 * (1.f / EDIM) - mu * mu;
    const float rs  = rsqrtf(var + 1e-5f);

    float4 gv = *(const float4*)(g + tid * 4);
    float4 bv = *(const float4*)(b + tid * 4);
    float4 o4;
    o4.x = (v.x - mu) * rs * gv.x + bv.x;
    o4.y = (v.y - mu) * rs * gv.y + bv.y;
    o4.z = (v.z - mu) * rs * gv.z + bv.z;
    o4.w = (v.w - mu) * rs * gv.w + bv.w;
    *(float4*)(y + (long long)row * EDIM + tid * 4) = o4;
}

// ---------------------------------------------------------------------------
// SGEMM NT: C[N,M] = A[N,K] @ B[M,K]^T + bias, with optional epilogue.
// 64x64x16 tile, 256 threads, 4x4 micro-tile per thread.
// EPI: 0 = bias only, 1 = bias + exact GELU, 2 = bias + residual add.
// All dims are multiples of the tile sizes (no bounds checks).
// ---------------------------------------------------------------------------
__device__ __forceinline__ float gelu_exact(float v) {
    return 0.5f * v * (1.0f + erff(v * 0.7071067811865476f));
}

template <int EPI>
__global__ __launch_bounds__(256) void gemm_nt(
    const float* __restrict__ A, const float* __restrict__ B,
    const float* __restrict__ bias, const float* __restrict__ resid,
    float* __restrict__ C, int N, int M, int K)
{
    constexpr int BM = 64, BN = 64, BK = 16;
    __shared__ float As[BK][68];   // [k][m], padded
    __shared__ float Bs[BK][68];   // [k][n], padded

    const int n0 = blockIdx.y * BM;
    const int m0 = blockIdx.x * BN;
    const int tid = threadIdx.x;
    const int tx = tid & 15;       // N (col) direction
    const int ty = tid >> 4;       // M (row) direction
    const int lrow = tid >> 2;     // 0..63
    const int lk   = (tid & 3) * 4;

    const float* Ab = A + (long long)(n0 + lrow) * K + lk;
    const float* Bb = B + (long long)(m0 + lrow) * K + lk;

    float acc[4][4] = {};

    for (int k0 = 0; k0 < K; k0 += BK) {
        const float4 a4 = *(const float4*)(Ab + k0);
        const float4 b4 = *(const float4*)(Bb + k0);
        __syncthreads();
        As[lk + 0][lrow] = a4.x; As[lk + 1][lrow] = a4.y;
        As[lk + 2][lrow] = a4.z; As[lk + 3][lrow] = a4.w;
        Bs[lk + 0][lrow] = b4.x; Bs[lk + 1][lrow] = b4.y;
        Bs[lk + 2][lrow] = b4.z; Bs[lk + 3][lrow] = b4.w;
        __syncthreads();

        #pragma unroll
        for (int k = 0; k < BK; k++) {
            const float4 a = *(const float4*)&As[k][ty * 4];
            const float4 b = *(const float4*)&Bs[k][tx * 4];
            acc[0][0] += a.x * b.x; acc[0][1] += a.x * b.y; acc[0][2] += a.x * b.z; acc[0][3] += a.x * b.w;
            acc[1][0] += a.y * b.x; acc[1][1] += a.y * b.y; acc[1][2] += a.y * b.z; acc[1][3] += a.y * b.w;
            acc[2][0] += a.z * b.x; acc[2][1] += a.z * b.y; acc[2][2] += a.z * b.z; acc[2][3] += a.z * b.w;
            acc[3][0] += a.w * b.x; acc[3][1] += a.w * b.y; acc[3][2] += a.w * b.z; acc[3][3] += a.w * b.w;
        }
    }

    const float4 bv = *(const float4*)(bias + m0 + tx * 4);
    #pragma unroll
    for (int i = 0; i < 4; i++) {
        const long long r = n0 + ty * 4 + i;
        float4 c;
        c.x = acc[i][0] + bv.x;
        c.y = acc[i][1] + bv.y;
        c.z = acc[i][2] + bv.z;
        c.w = acc[i][3] + bv.w;
        if (EPI == 1) {
            c.x = gelu_exact(c.x); c.y = gelu_exact(c.y);
            c.z = gelu_exact(c.z); c.w = gelu_exact(c.w);
        }
        if (EPI == 2) {
            const float4 rv = *(const float4*)(resid + r * M + m0 + tx * 4);
            c.x += rv.x; c.y += rv.y; c.z += rv.z; c.w += rv.w;
        }
        *(float4*)(C + r * M + m0 + tx * 4) = c;
    }
}

// ---------------------------------------------------------------------------
// Flash attention, fp32, D=64, 16 heads, S=2048 per batch.
// One block per (q-tile of 64, b*h). Online softmax with K-tiles of 32.
// qkv layout per token row (3072 floats): [comp(3), head(16), d(64)].
// ---------------------------------------------------------------------------
__global__ __launch_bounds__(256) void flash_attn(
    const float* __restrict__ qkv, float* __restrict__ out)
{
    constexpr int BQ = 64, BKt = 32, D = HDIM;
    __shared__ float Qs[D][BQ];        // transposed: Qs[d][i]
    __shared__ float Ks[D][BKt];       // transposed: Ks[d][j]
    __shared__ float Vs[BKt][D];       // Vs[j][d]
    __shared__ float Ss[BQ][BKt + 1];  // scores / probs, padded
    __shared__ float m_s[BQ], l_s[BQ], fac_s[BQ];

    const int tid = threadIdx.x;
    const int bh = blockIdx.y;
    const int b = bh >> 4;
    const int h = bh & 15;
    const int q0 = blockIdx.x * BQ;
    const float scale = 0.125f;  // D^-0.5

    const float* base = qkv + (long long)b * SEQ * (3 * EDIM) + h * HDIM;

    // Load Q tile (transposed into Qs)
    {
        const int i  = tid >> 2;
        const int d4 = (tid & 3) * 4;
        const float* qrow = base + (long long)(q0 + i) * (3 * EDIM);
        #pragma unroll
        for (int dd = 0; dd < 4; dd++) {
            const int d = dd * 16 + d4;
            const float4 v = *(const float4*)(qrow + d);
            Qs[d + 0][i] = v.x; Qs[d + 1][i] = v.y;
            Qs[d + 2][i] = v.z; Qs[d + 3][i] = v.w;
        }
    }
    if (tid < BQ) { m_s[tid] = -3.0e38f; l_s[tid] = 0.f; }

    float oacc[4][4] = {};
    const int tx = tid & 15, ty = tid >> 4;

    for (int kt = 0; kt < SEQ; kt += BKt) {
        __syncthreads();  // protect Ks/Vs/Ss from previous iteration (and order init/Q)

        // Load K (transposed) and V (direct)
        {
            const int j  = tid >> 3;            // 0..31
            const int d8 = (tid & 7) * 8;       // 0..56
            const float* krow = base + EDIM + (long long)(kt + j) * (3 * EDIM);
            const float4 v0 = *(const float4*)(krow + d8);
            const float4 v1 = *(const float4*)(krow + d8 + 4);
            Ks[d8 + 0][j] = v0.x; Ks[d8 + 1][j] = v0.y;
            Ks[d8 + 2][j] = v0.z; Ks[d8 + 3][j] = v0.w;
            Ks[d8 + 4][j] = v1.x; Ks[d8 + 5][j] = v1.y;
            Ks[d8 + 6][j] = v1.z; Ks[d8 + 7][j] = v1.w;

            #pragma unroll
            for (int e = 0; e < 2; e++) {
                const int idx = tid + e * 256;       // float4 index, 0..511
                const int jj = idx >> 4;
                const int dv = (idx & 15) * 4;
                const float* vrow = base + 2 * EDIM + (long long)(kt + jj) * (3 * EDIM);
                *(float4*)&Vs[jj][dv] = *(const float4*)(vrow + dv);
            }
        }
        __syncthreads();

        // Scores: each thread computes 4 rows x 2 cols
        {
            float s00 = 0, s01 = 0, s10 = 0, s11 = 0, s20 = 0, s21 = 0, s30 = 0, s31 = 0;
            #pragma unroll
            for (int d = 0; d < D; d++) {
                const float4 a = *(const float4*)&Qs[d][ty * 4];
                const float2 bk = *(const float2*)&Ks[d][tx * 2];
                s00 += a.x * bk.x; s01 += a.x * bk.y;
                s10 += a.y * bk.x; s11 += a.y * bk.y;
                s20 += a.z * bk.x; s21 += a.z * bk.y;
                s30 += a.w * bk.x; s31 += a.w * bk.y;
            }
            const int r = ty * 4, c = tx * 2;
            Ss[r + 0][c] = s00 * scale; Ss[r + 0][c + 1] = s01 * scale;
            Ss[r + 1][c] = s10 * scale; Ss[r + 1][c + 1] = s11 * scale;
            Ss[r + 2][c] = s20 * scale; Ss[r + 2][c + 1] = s21 * scale;
            Ss[r + 3][c] = s30 * scale; Ss[r + 3][c + 1] = s31 * scale;
        }
        __syncthreads();

        // Online softmax: 4 lanes per row, 8 entries each
        {
            const int r = tid >> 2;
            const int l4 = tid & 3;
            float vals[8];
            float mloc = -3.0e38f;
            #pragma unroll
            for (int e = 0; e < 8; e++) {
                vals[e] = Ss[r][l4 * 8 + e];
                mloc = fmaxf(mloc, vals[e]);
            }
            mloc = fmaxf(mloc, __shfl_xor_sync(0xffffffffu, mloc, 1));
            mloc = fmaxf(mloc, __shfl_xor_sync(0xffffffffu, mloc, 2));
            const float mold = m_s[r];
            const float mnew = fmaxf(mold, mloc);
            float sum = 0.f;
            #pragma unroll
            for (int e = 0; e < 8; e++) {
                const float p = __expf(vals[e] - mnew);
                Ss[r][l4 * 8 + e] = p;
                sum += p;
            }
            sum += __shfl_xor_sync(0xffffffffu, sum, 1);
            sum += __shfl_xor_sync(0xffffffffu, sum, 2);
            if (l4 == 0) {
                const float f = __expf(mold - mnew);
                fac_s[r] = f;
                m_s[r] = mnew;
                l_s[r] = l_s[r] * f + sum;
            }
        }
        __syncthreads();

        // Rescale accumulators + P@V
        {
            #pragma unroll
            for (int i = 0; i < 4; i++) {
                const float f = fac_s[ty * 4 + i];
                oacc[i][0] *= f; oacc[i][1] *= f; oacc[i][2] *= f; oacc[i][3] *= f;
            }
            #pragma unroll
            for (int j = 0; j < BKt; j++) {
                const float4 v = *(const float4*)&Vs[j][tx * 4];
                const float p0 = Ss[ty * 4 + 0][j];
                const float p1 = Ss[ty * 4 + 1][j];
                const float p2 = Ss[ty * 4 + 2][j];
                const float p3 = Ss[ty * 4 + 3][j];
                oacc[0][0] += p0 * v.x; oacc[0][1] += p0 * v.y; oacc[0][2] += p0 * v.z; oacc[0][3] += p0 * v.w;
                oacc[1][0] += p1 * v.x; oacc[1][1] += p1 * v.y; oacc[1][2] += p1 * v.z; oacc[1][3] += p1 * v.w;
                oacc[2][0] += p2 * v.x; oacc[2][1] += p2 * v.y; oacc[2][2] += p2 * v.z; oacc[2][3] += p2 * v.w;
                oacc[3][0] += p3 * v.x; oacc[3][1] += p3 * v.y; oacc[3][2] += p3 * v.z; oacc[3][3] += p3 * v.w;
            }
        }
    }

    // Write normalized output: out[(b*S + q0 + r) * E + h*64 + tx*4 .. +3]
    #pragma unroll
    for (int i = 0; i < 4; i++) {
        const int r = ty * 4 + i;
        const float inv = 1.0f / l_s[r];
        float4 res;
        res.x = oacc[i][0] * inv; res.y = oacc[i][1] * inv;
        res.z = oacc[i][2] * inv; res.w = oacc[i][3] * inv;
        *(float4*)(out + (long long)(b * SEQ + q0 + r) * EDIM + h * HDIM + tx * 4) = res;
    }
}

// ---------------------------------------------------------------------------
// Launch: LN1 -> QKV -> attention -> out-proj(+res) -> LN2 -> FF1(GELU) ->
// FF2(+res, writes d_out). All on default stream (graph-capturable).
// ---------------------------------------------------------------------------
extern "C" void kernel_launch(void* const* d_in, const int* in_sizes, int n_in,
                              void* d_out, int out_size)
{
    const float* x     = (const float*)d_in[0];
    const float* qkv_w = (const float*)d_in[1];
    const float* qkv_b = (const float*)d_in[2];
    const float* out_w = (const float*)d_in[3];
    const float* out_b = (const float*)d_in[4];
    const float* ff1_w = (const float*)d_in[5];
    const float* ff1_b = (const float*)d_in[6];
    const float* ff2_w = (const float*)d_in[7];
    const float* ff2_b = (const float*)d_in[8];
    const float* ln1_g = (const float*)d_in[9];
    const float* ln1_b = (const float*)d_in[10];
    const float* ln2_g = (const float*)d_in[11];
    const float* ln2_b = (const float*)d_in[12];
    float* out = (float*)d_out;

    float *p_h, *p_qkv, *p_o, *p_x1, *p_ff;
    cudaGetSymbolAddress((void**)&p_h,   g_h);
    cudaGetSymbolAddress((void**)&p_qkv, g_qkv);
    cudaGetSymbolAddress((void**)&p_o,   g_o);
    cudaGetSymbolAddress((void**)&p_x1,  g_x1);
    cudaGetSymbolAddress((void**)&p_ff,  g_ff);

    // 1. LN1
    ln_kernel<<<NTOK, 256>>>(x, ln1_g, ln1_b, p_h);
    // 2. QKV = h @ qkv_w^T + b   [4096, 3072]
    gemm_nt<0><<<dim3((3 * EDIM) / 64, NTOK / 64), 256>>>(
        p_h, qkv_w, qkv_b, nullptr, p_qkv, NTOK, 3 * EDIM, EDIM);
    // 3. Attention
    flash_attn<<<dim3(SEQ / 64, NB * NH), 256>>>(p_qkv, p_o);
    // 4. x1 = x + o @ out_w^T + b   [4096, 1024]
    gemm_nt<2><<<dim3(EDIM / 64, NTOK / 64), 256>>>(
        p_o, out_w, out_b, x, p_x1, NTOK, EDIM, EDIM);
    // 5. LN2
    ln_kernel<<<NTOK, 256>>>(p_x1, ln2_g, ln2_b, p_h);
    // 6. ff = GELU(h @ ff1_w^T + b)   [4096, 4096]
    gemm_nt<1><<<dim3(FDIM / 64, NTOK / 64), 256>>>(
        p_h, ff1_w, ff1_b, nullptr, p_ff, NTOK, FDIM, EDIM);
    // 7. out = x1 + ff @ ff2_w^T + b  [4096, 1024]
    gemm_nt<2><<<dim3(EDIM / 64, NTOK / 64), 256>>>(
        p_ff, ff2_w, ff2_b, p_x1, out, NTOK, EDIM, FDIM);
}

// round 16
// speedup vs baseline: 1.1116x; 1.1116x over previous
#include <cuda_runtime.h>
#include <math.h>

#define NTOK 4096   // B*S
#define EDIM 1024
#define FDIM 4096
#define SEQ  2048
#define NB   2
#define NH   16
#define HDIM 64

// Scratch (allocation-free rule: static __device__ globals)
__device__ float g_h  [NTOK * EDIM];      // LN1 / LN2 output (reused)
__device__ float g_qkv[NTOK * 3 * EDIM];  // fused qkv
__device__ float g_o  [NTOK * EDIM];      // attention output
__device__ float g_x1 [NTOK * EDIM];      // residual after attention
__device__ float g_ff [NTOK * FDIM];      // FF1 output

// ---------------------------------------------------------------------------
// LayerNorm over last dim (1024). One block per row, 256 threads.
// ---------------------------------------------------------------------------
__global__ __launch_bounds__(256) void ln_kernel(
    const float* __restrict__ x, const float* __restrict__ g,
    const float* __restrict__ b, float* __restrict__ y)
{
    const int row = blockIdx.x;
    const int tid = threadIdx.x;
    const float* xr = x + (long long)row * EDIM;

    float4 v = *(const float4*)(xr + tid * 4);
    float s  = v.x + v.y + v.z + v.w;
    float ss = v.x * v.x + v.y * v.y + v.z * v.z + v.w * v.w;

    #pragma unroll
    for (int o = 16; o; o >>= 1) {
        s  += __shfl_xor_sync(0xffffffffu, s,  o);
        ss += __shfl_xor_sync(0xffffffffu, ss, o);
    }
    __shared__ float sh_s[8], sh_ss[8];
    const int w = tid >> 5, l = tid & 31;
    if (l == 0) { sh_s[w] = s; sh_ss[w] = ss; }
    __syncthreads();

    float tot = 0.f, tot2 = 0.f;
    #pragma unroll
    for (int i = 0; i < 8; i++) { tot += sh_s[i]; tot2 += sh_ss[i]; }

    const float mu  = tot  * (1.f / EDIM);
    const float var = tot2 * (1.f / EDIM) - mu * mu;
    const float rs  = rsqrtf(var + 1e-5f);

    float4 gv = *(const float4*)(g + tid * 4);
    float4 bv = *(const float4*)(b + tid * 4);
    float4 o4;
    o4.x = (v.x - mu) * rs * gv.x + bv.x;
    o4.y = (v.y - mu) * rs * gv.y + bv.y;
    o4.z = (v.z - mu) * rs * gv.z + bv.z;
    o4.w = (v.w - mu) * rs * gv.w + bv.w;
    *(float4*)(y + (long long)row * EDIM + tid * 4) = o4;
}

// ---------------------------------------------------------------------------
// SGEMM NT: C[N,M] = A[N,K] @ B[M,K]^T + bias, optional epilogue.
// 128x128x16 block tile, 256 threads, 8x8 micro-tile, double-buffered smem.
// EPI: 0 = bias, 1 = bias + exact GELU, 2 = bias + residual add.
// N, M multiples of 128; K multiple of 16.
// ---------------------------------------------------------------------------
__device__ __forceinline__ float gelu_exact(float v) {
    return 0.5f * v * (1.0f + erff(v * 0.7071067811865476f));
}

template <int EPI>
__global__ __launch_bounds__(256) void gemm_nt(
    const float* __restrict__ A, const float* __restrict__ B,
    const float* __restrict__ bias, const float* __restrict__ resid,
    float* __restrict__ C, int N, int M, int K)
{
    constexpr int BT = 128, BK = 16, PAD = 4;
    __shared__ float As[2][BK][BT + PAD];   // [k][n]
    __shared__ float Bs[2][BK][BT + PAD];   // [k][m]

    const int n0 = blockIdx.y * BT;
    const int m0 = blockIdx.x * BT;
    const int tid = threadIdx.x;
    const int tx = tid & 15;       // col dir
    const int ty = tid >> 4;       // row dir

    // Loader mapping: each thread loads 2 float4 per operand per tile.
    const int lrow = tid >> 2;           // 0..63
    const int lk   = (tid & 3) * 4;      // 0,4,8,12

    const float* Aptr = A + (long long)(n0 + lrow) * K + lk;
    const float* Bptr = B + (long long)(m0 + lrow) * K + lk;
    const long long off64 = 64LL * K;

    float acc[8][8] = {};
    float4 pa0, pa1, pb0, pb1;

    // Prologue: tile 0
    pa0 = *(const float4*)(Aptr);
    pa1 = *(const float4*)(Aptr + off64);
    pb0 = *(const float4*)(Bptr);
    pb1 = *(const float4*)(Bptr + off64);
    {
        As[0][lk + 0][lrow] = pa0.x; As[0][lk + 1][lrow] = pa0.y;
        As[0][lk + 2][lrow] = pa0.z; As[0][lk + 3][lrow] = pa0.w;
        As[0][lk + 0][lrow + 64] = pa1.x; As[0][lk + 1][lrow + 64] = pa1.y;
        As[0][lk + 2][lrow + 64] = pa1.z; As[0][lk + 3][lrow + 64] = pa1.w;
        Bs[0][lk + 0][lrow] = pb0.x; Bs[0][lk + 1][lrow] = pb0.y;
        Bs[0][lk + 2][lrow] = pb0.z; Bs[0][lk + 3][lrow] = pb0.w;
        Bs[0][lk + 0][lrow + 64] = pb1.x; Bs[0][lk + 1][lrow + 64] = pb1.y;
        Bs[0][lk + 2][lrow + 64] = pb1.z; Bs[0][lk + 3][lrow + 64] = pb1.w;
    }
    __syncthreads();

    const int nk = K / BK;
    int buf = 0;

    for (int t = 0; t < nk; t++) {
        const bool has_next = (t + 1 < nk);
        if (has_next) {
            const int k0 = (t + 1) * BK;
            pa0 = *(const float4*)(Aptr + k0);
            pa1 = *(const float4*)(Aptr + off64 + k0);
            pb0 = *(const float4*)(Bptr + k0);
            pb1 = *(const float4*)(Bptr + off64 + k0);
        }

        #pragma unroll
        for (int k = 0; k < BK; k++) {
            const float4 a0 = *(const float4*)&As[buf][k][ty * 4];
            const float4 a1 = *(const float4*)&As[buf][k][ty * 4 + 64];
            const float4 b0 = *(const float4*)&Bs[buf][k][tx * 4];
            const float4 b1 = *(const float4*)&Bs[buf][k][tx * 4 + 64];
            const float av[8] = {a0.x, a0.y, a0.z, a0.w, a1.x, a1.y, a1.z, a1.w};
            const float bv[8] = {b0.x, b0.y, b0.z, b0.w, b1.x, b1.y, b1.z, b1.w};
            #pragma unroll
            for (int i = 0; i < 8; i++)
                #pragma unroll
                for (int j = 0; j < 8; j++)
                    acc[i][j] += av[i] * bv[j];
        }

        if (has_next) {
            const int nb = buf ^ 1;
            As[nb][lk + 0][lrow] = pa0.x; As[nb][lk + 1][lrow] = pa0.y;
            As[nb][lk + 2][lrow] = pa0.z; As[nb][lk + 3][lrow] = pa0.w;
            As[nb][lk + 0][lrow + 64] = pa1.x; As[nb][lk + 1][lrow + 64] = pa1.y;
            As[nb][lk + 2][lrow + 64] = pa1.z; As[nb][lk + 3][lrow + 64] = pa1.w;
            Bs[nb][lk + 0][lrow] = pb0.x; Bs[nb][lk + 1][lrow] = pb0.y;
            Bs[nb][lk + 2][lrow] = pb0.z; Bs[nb][lk + 3][lrow] = pb0.w;
            Bs[nb][lk + 0][lrow + 64] = pb1.x; Bs[nb][lk + 1][lrow + 64] = pb1.y;
            Bs[nb][lk + 2][lrow + 64] = pb1.z; Bs[nb][lk + 3][lrow + 64] = pb1.w;
            __syncthreads();
        }
        buf ^= 1;
    }

    // Epilogue
    const float4 bvec0 = *(const float4*)(bias + m0 + tx * 4);
    const float4 bvec1 = *(const float4*)(bias + m0 + tx * 4 + 64);
    #pragma unroll
    for (int ri = 0; ri < 2; ri++) {
        #pragma unroll
        for (int i = 0; i < 4; i++) {
            const long long r = n0 + ri * 64 + ty * 4 + i;
            #pragma unroll
            for (int ci = 0; ci < 2; ci++) {
                const int col = m0 + ci * 64 + tx * 4;
                const float4 bb = ci ? bvec1 : bvec0;
                float4 c;
                c.x = acc[ri * 4 + i][ci * 4 + 0] + bb.x;
                c.y = acc[ri * 4 + i][ci * 4 + 1] + bb.y;
                c.z = acc[ri * 4 + i][ci * 4 + 2] + bb.z;
                c.w = acc[ri * 4 + i][ci * 4 + 3] + bb.w;
                if (EPI == 1) {
                    c.x = gelu_exact(c.x); c.y = gelu_exact(c.y);
                    c.z = gelu_exact(c.z); c.w = gelu_exact(c.w);
                }
                if (EPI == 2) {
                    const float4 rv = *(const float4*)(resid + r * M + col);
                    c.x += rv.x; c.y += rv.y; c.z += rv.z; c.w += rv.w;
                }
                *(float4*)(C + r * M + col) = c;
            }
        }
    }
}

// ---------------------------------------------------------------------------
// Flash attention, fp32, D=64, 16 heads, S=2048 per batch. (unchanged — proven)
// One block per (q-tile of 64, b*h). Online softmax with K-tiles of 32.
// qkv layout per token row (3072 floats): [comp(3), head(16), d(64)].
// ---------------------------------------------------------------------------
__global__ __launch_bounds__(256) void flash_attn(
    const float* __restrict__ qkv, float* __restrict__ out)
{
    constexpr int BQ = 64, BKt = 32, D = HDIM;
    __shared__ float Qs[D][BQ];        // transposed: Qs[d][i]
    __shared__ float Ks[D][BKt];       // transposed: Ks[d][j]
    __shared__ float Vs[BKt][D];       // Vs[j][d]
    __shared__ float Ss[BQ][BKt + 1];  // scores / probs, padded
    __shared__ float m_s[BQ], l_s[BQ], fac_s[BQ];

    const int tid = threadIdx.x;
    const int bh = blockIdx.y;
    const int b = bh >> 4;
    const int h = bh & 15;
    const int q0 = blockIdx.x * BQ;
    const float scale = 0.125f;  // D^-0.5

    const float* base = qkv + (long long)b * SEQ * (3 * EDIM) + h * HDIM;

    // Load Q tile (transposed into Qs)
    {
        const int i  = tid >> 2;
        const int d4 = (tid & 3) * 4;
        const float* qrow = base + (long long)(q0 + i) * (3 * EDIM);
        #pragma unroll
        for (int dd = 0; dd < 4; dd++) {
            const int d = dd * 16 + d4;
            const float4 v = *(const float4*)(qrow + d);
            Qs[d + 0][i] = v.x; Qs[d + 1][i] = v.y;
            Qs[d + 2][i] = v.z; Qs[d + 3][i] = v.w;
        }
    }
    if (tid < BQ) { m_s[tid] = -3.0e38f; l_s[tid] = 0.f; }

    float oacc[4][4] = {};
    const int tx = tid & 15, ty = tid >> 4;

    for (int kt = 0; kt < SEQ; kt += BKt) {
        __syncthreads();

        // Load K (transposed) and V (direct)
        {
            const int j  = tid >> 3;            // 0..31
            const int d8 = (tid & 7) * 8;       // 0..56
            const float* krow = base + EDIM + (long long)(kt + j) * (3 * EDIM);
            const float4 v0 = *(const float4*)(krow + d8);
            const float4 v1 = *(const float4*)(krow + d8 + 4);
            Ks[d8 + 0][j] = v0.x; Ks[d8 + 1][j] = v0.y;
            Ks[d8 + 2][j] = v0.z; Ks[d8 + 3][j] = v0.w;
            Ks[d8 + 4][j] = v1.x; Ks[d8 + 5][j] = v1.y;
            Ks[d8 + 6][j] = v1.z; Ks[d8 + 7][j] = v1.w;

            #pragma unroll
            for (int e = 0; e < 2; e++) {
                const int idx = tid + e * 256;       // float4 index, 0..511
                const int jj = idx >> 4;
                const int dv = (idx & 15) * 4;
                const float* vrow = base + 2 * EDIM + (long long)(kt + jj) * (3 * EDIM);
                *(float4*)&Vs[jj][dv] = *(const float4*)(vrow + dv);
            }
        }
        __syncthreads();

        // Scores: each thread computes 4 rows x 2 cols
        {
            float s00 = 0, s01 = 0, s10 = 0, s11 = 0, s20 = 0, s21 = 0, s30 = 0, s31 = 0;
            #pragma unroll
            for (int d = 0; d < D; d++) {
                const float4 a = *(const float4*)&Qs[d][ty * 4];
                const float2 bk = *(const float2*)&Ks[d][tx * 2];
                s00 += a.x * bk.x; s01 += a.x * bk.y;
                s10 += a.y * bk.x; s11 += a.y * bk.y;
                s20 += a.z * bk.x; s21 += a.z * bk.y;
                s30 += a.w * bk.x; s31 += a.w * bk.y;
            }
            const int r = ty * 4, c = tx * 2;
            Ss[r + 0][c] = s00 * scale; Ss[r + 0][c + 1] = s01 * scale;
            Ss[r + 1][c] = s10 * scale; Ss[r + 1][c + 1] = s11 * scale;
            Ss[r + 2][c] = s20 * scale; Ss[r + 2][c + 1] = s21 * scale;
            Ss[r + 3][c] = s30 * scale; Ss[r + 3][c + 1] = s31 * scale;
        }
        __syncthreads();

        // Online softmax: 4 lanes per row, 8 entries each
        {
            const int r = tid >> 2;
            const int l4 = tid & 3;
            float vals[8];
            float mloc = -3.0e38f;
            #pragma unroll
            for (int e = 0; e < 8; e++) {
                vals[e] = Ss[r][l4 * 8 + e];
                mloc = fmaxf(mloc, vals[e]);
            }
            mloc = fmaxf(mloc, __shfl_xor_sync(0xffffffffu, mloc, 1));
            mloc = fmaxf(mloc, __shfl_xor_sync(0xffffffffu, mloc, 2));
            const float mold = m_s[r];
            const float mnew = fmaxf(mold, mloc);
            float sum = 0.f;
            #pragma unroll
            for (int e = 0; e < 8; e++) {
                const float p = __expf(vals[e] - mnew);
                Ss[r][l4 * 8 + e] = p;
                sum += p;
            }
            sum += __shfl_xor_sync(0xffffffffu, sum, 1);
            sum += __shfl_xor_sync(0xffffffffu, sum, 2);
            if (l4 == 0) {
                const float f = __expf(mold - mnew);
                fac_s[r] = f;
                m_s[r] = mnew;
                l_s[r] = l_s[r] * f + sum;
            }
        }
        __syncthreads();

        // Rescale accumulators + P@V
        {
            #pragma unroll
            for (int i = 0; i < 4; i++) {
                const float f = fac_s[ty * 4 + i];
                oacc[i][0] *= f; oacc[i][1] *= f; oacc[i][2] *= f; oacc[i][3] *= f;
            }
            #pragma unroll
            for (int j = 0; j < BKt; j++) {
                const float4 v = *(const float4*)&Vs[j][tx * 4];
                const float p0 = Ss[ty * 4 + 0][j];
                const float p1 = Ss[ty * 4 + 1][j];
                const float p2 = Ss[ty * 4 + 2][j];
                const float p3 = Ss[ty * 4 + 3][j];
                oacc[0][0] += p0 * v.x; oacc[0][1] += p0 * v.y; oacc[0][2] += p0 * v.z; oacc[0][3] += p0 * v.w;
                oacc[1][0] += p1 * v.x; oacc[1][1] += p1 * v.y; oacc[1][2] += p1 * v.z; oacc[1][3] += p1 * v.w;
                oacc[2][0] += p2 * v.x; oacc[2][1] += p2 * v.y; oacc[2][2] += p2 * v.z; oacc[2][3] += p2 * v.w;
                oacc[3][0] += p3 * v.x; oacc[3][1] += p3 * v.y; oacc[3][2] += p3 * v.z; oacc[3][3] += p3 * v.w;
            }
        }
    }

    // Write normalized output
    #pragma unroll
    for (int i = 0; i < 4; i++) {
        const int r = ty * 4 + i;
        const float inv = 1.0f / l_s[r];
        float4 res;
        res.x = oacc[i][0] * inv; res.y = oacc[i][1] * inv;
        res.z = oacc[i][2] * inv; res.w = oacc[i][3] * inv;
        *(float4*)(out + (long long)(b * SEQ + q0 + r) * EDIM + h * HDIM + tx * 4) = res;
    }
}

// ---------------------------------------------------------------------------
// Launch sequence (default stream, graph-capturable).
// ---------------------------------------------------------------------------
extern "C" void kernel_launch(void* const* d_in, const int* in_sizes, int n_in,
                              void* d_out, int out_size)
{
    const float* x     = (const float*)d_in[0];
    const float* qkv_w = (const float*)d_in[1];
    const float* qkv_b = (const float*)d_in[2];
    const float* out_w = (const float*)d_in[3];
    const float* out_b = (const float*)d_in[4];
    const float* ff1_w = (const float*)d_in[5];
    const float* ff1_b = (const float*)d_in[6];
    const float* ff2_w = (const float*)d_in[7];
    const float* ff2_b = (const float*)d_in[8];
    const float* ln1_g = (const float*)d_in[9];
    const float* ln1_b = (const float*)d_in[10];
    const float* ln2_g = (const float*)d_in[11];
    const float* ln2_b = (const float*)d_in[12];
    float* out = (float*)d_out;

    float *p_h, *p_qkv, *p_o, *p_x1, *p_ff;
    cudaGetSymbolAddress((void**)&p_h,   g_h);
    cudaGetSymbolAddress((void**)&p_qkv, g_qkv);
    cudaGetSymbolAddress((void**)&p_o,   g_o);
    cudaGetSymbolAddress((void**)&p_x1,  g_x1);
    cudaGetSymbolAddress((void**)&p_ff,  g_ff);

    // 1. LN1
    ln_kernel<<<NTOK, 256>>>(x, ln1_g, ln1_b, p_h);
    // 2. QKV = h @ qkv_w^T + b   [4096, 3072]
    gemm_nt<0><<<dim3((3 * EDIM) / 128, NTOK / 128), 256>>>(
        p_h, qkv_w, qkv_b, nullptr, p_qkv, NTOK, 3 * EDIM, EDIM);
    // 3. Attention
    flash_attn<<<dim3(SEQ / 64, NB * NH), 256>>>(p_qkv, p_o);
    // 4. x1 = x + o @ out_w^T + b   [4096, 1024]
    gemm_nt<2><<<dim3(EDIM / 128, NTOK / 128), 256>>>(
        p_o, out_w, out_b, x, p_x1, NTOK, EDIM, EDIM);
    // 5. LN2
    ln_kernel<<<NTOK, 256>>>(p_x1, ln2_g, ln2_b, p_h);
    // 6. ff = GELU(h @ ff1_w^T + b)   [4096, 4096]
    gemm_nt<1><<<dim3(FDIM / 128, NTOK / 128), 256>>>(
        p_h, ff1_w, ff1_b, nullptr, p_ff, NTOK, FDIM, EDIM);
    // 7. out = x1 + ff @ ff2_w^T + b  [4096, 1024]
    gemm_nt<2><<<dim3(EDIM / 128, NTOK / 128), 256>>>(
        p_ff, ff2_w, ff2_b, p_x1, out, NTOK, EDIM, FDIM);
}